// round 1
// baseline (speedup 1.0000x reference)
#include <cuda_runtime.h>
#include <math.h>
#include <stdint.h>

#define MAXROWS 100000
#define IN_DIM 1152
#define HID    1024
#define ODIM   512

// ---------------- scratch (device globals: allocation-free rule) ----------------
__device__ float g_x1[(size_t)MAXROWS * IN_DIM];   // 460.8 MB
__device__ float g_h [(size_t)MAXROWS * HID];      // 409.6 MB
__device__ float g_y [(size_t)MAXROWS * ODIM];     // 204.8 MB
__device__ float g_w1[(size_t)IN_DIM * HID];
__device__ float g_w2[(size_t)HID * ODIM];

// round fp32 -> tf32 (round-to-nearest, keeps fp32 container)
__device__ __forceinline__ float tf32r(float x) {
    uint32_t u;
    asm("cvt.rna.tf32.f32 %0, %1;" : "=r"(u) : "f"(x));
    return __uint_as_float(u);
}

// ---------------- weight rounding ----------------
__global__ void round_copy_kernel(float* __restrict__ dst, const float* __restrict__ src, int n) {
    int i = blockIdx.x * blockDim.x + threadIdx.x;
    if (i < n) dst[i] = tf32r(src[i]);
}

// ---------------- prep: build x1 rows ----------------
// x1 = [ x[:,0] (128) | vec_local f-major (384) | vec_norm (128) | extra (512) ]
__global__ void prep_kernel(const float* __restrict__ x,
                            const float* __restrict__ rot,
                            const float* __restrict__ extra) {
    int n = blockIdx.x;
    int f = threadIdx.x;            // 128 threads
    __shared__ float R[9];
    if (f < 9) R[f] = rot[(size_t)n * 9 + f];
    __syncthreads();

    const float* xr = x + (size_t)n * 512;
    float x0 = xr[f];
    float v1 = xr[128 + f];
    float v2 = xr[256 + f];
    float v3 = xr[384 + f];

    float* o = g_x1 + (size_t)n * IN_DIM;
    o[f] = tf32r(x0);
#pragma unroll
    for (int k = 0; k < 3; ++k)
        o[128 + 3 * f + k] = tf32r(v1 * R[k] + v2 * R[3 + k] + v3 * R[6 + k]);
    o[512 + f] = tf32r(sqrtf(v1 * v1 + v2 * v2 + v3 * v3 + 1e-4f));

    const float* e = extra + (size_t)n * 512;
#pragma unroll
    for (int j = 0; j < 4; ++j)
        o[640 + f + 128 * j] = tf32r(e[f + 128 * j]);
}

// ---------------- tiled tf32 GEMM: C(MxN) = A(MxK) @ B(KxN) + bias, optional GELU ----------------
// Block tile 128x128, K-tile 32, 256 threads = 8 warps (2x4), warp tile 64x32,
// mma.sync.m16n8k8 tf32. Double-buffered smem, conflict-free fragment strides.
#define SA_STRIDE 36   // 128x(32+4): 36g+t mod 32 = 4g+t -> conflict-free A frags
#define SB_STRIDE 136  // 32x(128+8): 136t mod 32 = 8t   -> conflict-free B frags
#define SA_STAGE (128 * SA_STRIDE)
#define SB_STAGE (32 * SB_STRIDE)
#define SMEM_FLOATS (2 * SA_STAGE + 2 * SB_STAGE)   // 17920 floats = 71680 B

template<int GELU_EPI>
__global__ void __launch_bounds__(256)
gemm_tf32_kernel(const float* __restrict__ A, const float* __restrict__ B,
                 const float* __restrict__ bias, float* __restrict__ C,
                 int M, int K, int N) {
    extern __shared__ float smem[];
    float* sA = smem;                 // [2][128][36]
    float* sB = smem + 2 * SA_STAGE;  // [2][32][136]

    const int tid  = threadIdx.x;
    const int lane = tid & 31;
    const int warp = tid >> 5;
    const int wm = (warp >> 2) * 64;   // warp row offset in tile
    const int wn = (warp & 3) * 32;    // warp col offset in tile
    const int g = lane >> 2;           // groupID
    const int t = lane & 3;            // threadID in group

    const int rowBase = blockIdx.y * 128;
    const int colBase = blockIdx.x * 128;

    // global->reg staging mapping
    const int ar  = tid >> 3;          // A row (0..31), +32p
    const int ac4 = (tid & 7) << 2;    // A col (float4)
    const int br  = tid >> 5;          // B row (0..7), +8p
    const int bc4 = lane << 2;         // B col (float4)

    float acc[4][4][4];
#pragma unroll
    for (int i = 0; i < 4; ++i)
#pragma unroll
        for (int j = 0; j < 4; ++j)
#pragma unroll
            for (int r = 0; r < 4; ++r) acc[i][j][r] = 0.0f;

    float4 pa[4], pb[4];

    auto loadA = [&](int kt) {
#pragma unroll
        for (int p = 0; p < 4; ++p) {
            int row = rowBase + ar + 32 * p;
            if (row < M) pa[p] = *(const float4*)(A + (size_t)row * K + kt + ac4);
            else         pa[p] = make_float4(0.f, 0.f, 0.f, 0.f);
        }
    };
    auto loadB = [&](int kt) {
#pragma unroll
        for (int p = 0; p < 4; ++p)
            pb[p] = *(const float4*)(B + (size_t)(kt + br + 8 * p) * N + colBase + bc4);
    };
    auto stageStore = [&](int s) {
#pragma unroll
        for (int p = 0; p < 4; ++p)
            *(float4*)(sA + s * SA_STAGE + (ar + 32 * p) * SA_STRIDE + ac4) = pa[p];
#pragma unroll
        for (int p = 0; p < 4; ++p)
            *(float4*)(sB + s * SB_STAGE + (br + 8 * p) * SB_STRIDE + bc4) = pb[p];
    };

    const int T = K / 32;
    loadA(0); loadB(0);
    stageStore(0);
    __syncthreads();

    for (int tt = 0; tt < T; ++tt) {
        const int s = tt & 1;
        if (tt + 1 < T) { loadA((tt + 1) * 32); loadB((tt + 1) * 32); }

#pragma unroll
        for (int kk = 0; kk < 32; kk += 8) {
            uint32_t afr[4][4];
            uint32_t bfr[4][2];
#pragma unroll
            for (int i = 0; i < 4; ++i) {
                const float* base = sA + s * SA_STAGE + kk + t;
                int r0 = wm + 16 * i + g;
                afr[i][0] = __float_as_uint(base[(r0    ) * SA_STRIDE    ]);
                afr[i][1] = __float_as_uint(base[(r0 + 8) * SA_STRIDE    ]);
                afr[i][2] = __float_as_uint(base[(r0    ) * SA_STRIDE + 4]);
                afr[i][3] = __float_as_uint(base[(r0 + 8) * SA_STRIDE + 4]);
            }
#pragma unroll
            for (int j = 0; j < 4; ++j) {
                const float* base = sB + s * SB_STAGE + (kk + t) * SB_STRIDE + wn + 8 * j + g;
                bfr[j][0] = __float_as_uint(base[0]);
                bfr[j][1] = __float_as_uint(base[4 * SB_STRIDE]);
            }
#pragma unroll
            for (int i = 0; i < 4; ++i)
#pragma unroll
                for (int j = 0; j < 4; ++j)
                    asm volatile(
                        "mma.sync.aligned.m16n8k8.row.col.f32.tf32.tf32.f32 "
                        "{%0,%1,%2,%3}, {%4,%5,%6,%7}, {%8,%9}, {%0,%1,%2,%3};"
                        : "+f"(acc[i][j][0]), "+f"(acc[i][j][1]),
                          "+f"(acc[i][j][2]), "+f"(acc[i][j][3])
                        : "r"(afr[i][0]), "r"(afr[i][1]), "r"(afr[i][2]), "r"(afr[i][3]),
                          "r"(bfr[j][0]), "r"(bfr[j][1]));
        }

        if (tt + 1 < T) {
            __syncthreads();
            stageStore(s ^ 1);
            __syncthreads();
        }
    }

    // epilogue: bias (+ exact GELU + tf32 round for layer 1)
#pragma unroll
    for (int i = 0; i < 4; ++i) {
        int r0 = rowBase + wm + 16 * i + g;
#pragma unroll
        for (int j = 0; j < 4; ++j) {
            int col = colBase + wn + 8 * j + 2 * t;
            float bv0 = bias[col], bv1 = bias[col + 1];
#pragma unroll
            for (int rr = 0; rr < 2; ++rr) {
                int row = r0 + 8 * rr;
                if (row < M) {
                    float v0 = acc[i][j][2 * rr + 0] + bv0;
                    float v1 = acc[i][j][2 * rr + 1] + bv1;
                    if (GELU_EPI) {
                        v0 = 0.5f * v0 * (1.0f + erff(v0 * 0.70710678118654752f));
                        v1 = 0.5f * v1 * (1.0f + erff(v1 * 0.70710678118654752f));
                        v0 = tf32r(v0);  // feeds GEMM2 as tf32
                        v1 = tf32r(v1);
                    }
                    *(float2*)(C + (size_t)row * N + col) = make_float2(v0, v1);
                }
            }
        }
    }
}

// ---------------- finalize: out0 = y0 ; out[c] = R @ y[1:4] ----------------
__global__ void finalize_kernel(const float* __restrict__ rot, float* __restrict__ out) {
    int n = blockIdx.x;
    int f = threadIdx.x;   // 128 threads
    __shared__ float R[9];
    if (f < 9) R[f] = rot[(size_t)n * 9 + f];
    __syncthreads();

    const float* y = g_y + (size_t)n * ODIM;
    float y0 = y[f], y1 = y[128 + f], y2 = y[256 + f], y3 = y[384 + f];

    float* o = out + (size_t)n * ODIM;
    o[f] = y0;
#pragma unroll
    for (int c = 0; c < 3; ++c)
        o[(c + 1) * 128 + f] = R[c * 3 + 0] * y1 + R[c * 3 + 1] * y2 + R[c * 3 + 2] * y3;
}

// ---------------- launch ----------------
extern "C" void kernel_launch(void* const* d_in, const int* in_sizes, int n_in,
                              void* d_out, int out_size) {
    const float* x     = (const float*)d_in[0];   // (N,4,128)
    const float* rot   = (const float*)d_in[1];   // (N,3,3)
    const float* extra = (const float*)d_in[2];   // (N,512)
    const float* W1    = (const float*)d_in[3];   // (1152,1024)
    const float* b1    = (const float*)d_in[4];   // (1024)
    const float* W2    = (const float*)d_in[5];   // (1024,512)
    const float* b2    = (const float*)d_in[6];   // (512)
    float* out = (float*)d_out;

    const int M = in_sizes[0] / 512;              // 100000

    void *px1, *ph, *py, *pw1, *pw2;
    cudaGetSymbolAddress(&px1, g_x1);
    cudaGetSymbolAddress(&ph,  g_h);
    cudaGetSymbolAddress(&py,  g_y);
    cudaGetSymbolAddress(&pw1, g_w1);
    cudaGetSymbolAddress(&pw2, g_w2);

    const int smemBytes = SMEM_FLOATS * (int)sizeof(float);   // 71680
    cudaFuncSetAttribute(gemm_tf32_kernel<1>, cudaFuncAttributeMaxDynamicSharedMemorySize, smemBytes);
    cudaFuncSetAttribute(gemm_tf32_kernel<0>, cudaFuncAttributeMaxDynamicSharedMemorySize, smemBytes);

    // 1) round weights to tf32
    {
        int n1 = IN_DIM * HID;
        round_copy_kernel<<<(n1 + 255) / 256, 256>>>((float*)pw1, W1, n1);
        int n2 = HID * ODIM;
        round_copy_kernel<<<(n2 + 255) / 256, 256>>>((float*)pw2, W2, n2);
    }

    // 2) build x1
    prep_kernel<<<M, 128>>>(x, rot, extra);

    // 3) h = tf32( gelu(x1 @ W1 + b1) )
    {
        dim3 grid(HID / 128, (M + 127) / 128);
        gemm_tf32_kernel<1><<<grid, 256, smemBytes>>>((const float*)px1, (const float*)pw1,
                                                      b1, (float*)ph, M, IN_DIM, HID);
    }

    // 4) y = h @ W2 + b2
    {
        dim3 grid(ODIM / 128, (M + 127) / 128);
        gemm_tf32_kernel<0><<<grid, 256, smemBytes>>>((const float*)ph, (const float*)pw2,
                                                      b2, (float*)py, M, HID, ODIM);
    }

    // 5) rotate back + assemble output
    finalize_kernel<<<M, 128>>>(rot, out);
}

// round 4
// speedup vs baseline: 2.3554x; 2.3554x over previous
#include <cuda_runtime.h>
#include <cuda_fp16.h>
#include <math.h>
#include <stdint.h>

// ================= problem constants =================
#define MCAP   100096              // 782*128 padded row capacity
#define K1     1152
#define HIDN   1024
#define ODIMN  512

// ================= scratch (device globals; allocation-free rule) =================
__device__ __half g_x1h[(size_t)MCAP * K1];     // x1, half, row-major, permuted cols
__device__ __half g_hh [(size_t)MCAP * HIDN];   // h,  half, row-major
__device__ float  g_y  [(size_t)MCAP * ODIMN];  // y,  fp32, row-major
__device__ __half g_w1t[(size_t)HIDN * K1];     // W1^T [N][K], permuted rows
__device__ __half g_w2t[(size_t)ODIMN * HIDN];  // W2^T [N][K]

// ================= helpers =================
__device__ __forceinline__ uint32_t smem_u32(const void* p) {
    uint32_t a;
    asm("{ .reg .u64 t; cvta.to.shared.u64 t, %1; cvt.u32.u64 %0, t; }" : "=r"(a) : "l"(p));
    return a;
}
// XOR swizzle: 16B chunk index (bits 4-6) ^ row%8 (bits 7-9), rows are 128B
__device__ __forceinline__ uint32_t swz(uint32_t b) { return b ^ ((b >> 3) & 0x70); }

__device__ __forceinline__ void cpa16(uint32_t dst, const void* src) {
    asm volatile("cp.async.cg.shared.global [%0], [%1], 16;" :: "r"(dst), "l"(src) : "memory");
}
#define CP_COMMIT() asm volatile("cp.async.commit_group;" ::: "memory")
#define CP_WAIT(n)  asm volatile("cp.async.wait_group %0;" :: "n"(n) : "memory")

// ================= prep: x1 (half, permuted cols, padded rows zeroed) =================
// new col order: [x0(128) | vl_j0(128) | vl_j1(128) | vl_j2(128) | norm(128) | extra(512)]
__global__ void prep_kernel(const float* __restrict__ x, const float* __restrict__ rot,
                            const float* __restrict__ extra, int Mreal) {
    int n = blockIdx.x, f = threadIdx.x;
    bool real = n < Mreal;
    __shared__ float R[9];
    if (real && f < 9) R[f] = rot[(size_t)n * 9 + f];
    __syncthreads();

    float x0 = 0.f, v1 = 0.f, v2 = 0.f, v3 = 0.f;
    if (real) {
        const float* xr = x + (size_t)n * 512;
        x0 = xr[f]; v1 = xr[128 + f]; v2 = xr[256 + f]; v3 = xr[384 + f];
    }
    __half* o = g_x1h + (size_t)n * K1;
    o[f] = __float2half(x0);
#pragma unroll
    for (int j = 0; j < 3; ++j) {
        float vl = real ? (v1 * R[j] + v2 * R[3 + j] + v3 * R[6 + j]) : 0.f;
        o[128 + 128 * j + f] = __float2half(vl);
    }
    o[512 + f] = __float2half(real ? sqrtf(v1 * v1 + v2 * v2 + v3 * v3 + 1e-4f) : 0.f);
#pragma unroll
    for (int j = 0; j < 4; ++j) {
        float e = real ? extra[(size_t)n * 512 + 128 * j + f] : 0.f;
        o[640 + 128 * j + f] = __float2half(e);
    }
}

// ================= weight prep: W[K][N] fp32 -> W^T[N][K] half (PERM row remap for W1) ======
template<int PERM>
__global__ void wprep_kernel(const float* __restrict__ W, __half* __restrict__ dst, int K, int N) {
    long t = (long)blockIdx.x * blockDim.x + threadIdx.x;
    if (t >= (long)N * K) return;
    int n = (int)(t / K), k = (int)(t % K);
    int nk = k;
    if (PERM && k >= 128 && k < 512) {
        int q = k - 128;
        nk = 128 + (q % 3) * 128 + (q / 3);
    }
    dst[(size_t)n * K + nk] = __float2half(W[(size_t)k * N + n]);
}

// ================= fp16 tensor-core GEMM =================
// C[M,ND] = A[M,KD] @ B^T  (B stored [ND][KD] half). Tile 128x128x64, 256 thr = 8 warps (2x4),
// warp tile 64x32, mma.m16n8k16.f32.f16.f16.f32, ldmatrix fragments, cp.async double buffer.
// GELU=1: out = half h rows (+bias+exact gelu).  GELU=0: out = fp32 y rows (+bias), row<Mreal.
template<int KD, int ND, int GELU>
__global__ void __launch_bounds__(256, 2)
gemm_h(const __half* __restrict__ A, const __half* __restrict__ B,
       const float* __restrict__ bias, void* __restrict__ outv, int Mreal) {
    extern __shared__ char smem[];
    const uint32_t sA = smem_u32(smem);          // 2 x 16KB
    const uint32_t sB = sA + 32768;              // 2 x 16KB

    const int tid = threadIdx.x, lane = tid & 31;
    const int warp = tid >> 5;
    const int wm = (warp >> 2) * 64, wn = (warp & 3) * 32;
    const int g = lane >> 2, t4 = lane & 3;
    const size_t rowBase = (size_t)blockIdx.y * 128;
    const int colBase = blockIdx.x * 128;

    // ldmatrix per-lane address components
    const int aSub = lane >> 3;
    const int aR = (lane & 7) + (aSub & 1) * 8;      // row within 16
    const int aK = (aSub >> 1) * 8;                  // k-half offset
    const int bR = lane & 7;
    const int bK = ((lane >> 3) & 1) * 8;

    float acc[4][4][4];
#pragma unroll
    for (int i = 0; i < 4; ++i)
#pragma unroll
        for (int j = 0; j < 4; ++j)
#pragma unroll
            for (int r = 0; r < 4; ++r) acc[i][j][r] = 0.0f;

    auto loadTile = [&](int k0, int s) {
#pragma unroll
        for (int p = 0; p < 4; ++p) {
            int idx = tid + p * 256;           // 1024 16B-chunks per operand
            int r = idx >> 3, c = idx & 7;     // row, 16B-chunk within 128B row
            cpa16(sA + s * 16384 + swz((uint32_t)(r * 128 + c * 16)),
                  A + (rowBase + r) * KD + k0 + c * 8);
            cpa16(sB + s * 16384 + swz((uint32_t)(r * 128 + c * 16)),
                  B + (size_t)(colBase + r) * KD + k0 + c * 8);
        }
    };

    const int T = KD / 64;
    loadTile(0, 0); CP_COMMIT();

    for (int tt = 0; tt < T; ++tt) {
        const int s = tt & 1;
        if (tt + 1 < T) { loadTile((tt + 1) * 64, s ^ 1); CP_COMMIT(); CP_WAIT(1); }
        else            { CP_WAIT(0); }
        __syncthreads();

#pragma unroll
        for (int kk = 0; kk < 64; kk += 16) {
            uint32_t af[4][4], bf[4][2];
#pragma unroll
            for (int i = 0; i < 4; ++i) {
                uint32_t a = sA + s * 16384 + swz((uint32_t)((wm + 16 * i + aR) * 128 + (kk + aK) * 2));
                asm volatile("ldmatrix.sync.aligned.m8n8.x4.shared.b16 {%0,%1,%2,%3}, [%4];"
                             : "=r"(af[i][0]), "=r"(af[i][1]), "=r"(af[i][2]), "=r"(af[i][3]) : "r"(a));
            }
#pragma unroll
            for (int j = 0; j < 4; ++j) {
                uint32_t a = sB + s * 16384 + swz((uint32_t)((wn + 8 * j + bR) * 128 + (kk + bK) * 2));
                asm volatile("ldmatrix.sync.aligned.m8n8.x2.shared.b16 {%0,%1}, [%2];"
                             : "=r"(bf[j][0]), "=r"(bf[j][1]) : "r"(a));
            }
#pragma unroll
            for (int i = 0; i < 4; ++i)
#pragma unroll
                for (int j = 0; j < 4; ++j)
                    asm volatile(
                        "mma.sync.aligned.m16n8k16.row.col.f32.f16.f16.f32 "
                        "{%0,%1,%2,%3}, {%4,%5,%6,%7}, {%8,%9}, {%0,%1,%2,%3};"
                        : "+f"(acc[i][j][0]), "+f"(acc[i][j][1]),
                          "+f"(acc[i][j][2]), "+f"(acc[i][j][3])
                        : "r"(af[i][0]), "r"(af[i][1]), "r"(af[i][2]), "r"(af[i][3]),
                          "r"(bf[j][0]), "r"(bf[j][1]));
        }
        __syncthreads();
    }

    // epilogue
#pragma unroll
    for (int i = 0; i < 4; ++i) {
        size_t r0 = rowBase + wm + 16 * i + g;
#pragma unroll
        for (int j = 0; j < 4; ++j) {
            int col = colBase + wn + 8 * j + 2 * t4;
            float b0 = bias[col], b1 = bias[col + 1];
#pragma unroll
            for (int rr = 0; rr < 2; ++rr) {
                size_t row = r0 + 8 * rr;
                float v0 = acc[i][j][2 * rr + 0] + b0;
                float v1 = acc[i][j][2 * rr + 1] + b1;
                if (GELU) {
                    v0 = 0.5f * v0 * (1.0f + erff(v0 * 0.70710678118654752f));
                    v1 = 0.5f * v1 * (1.0f + erff(v1 * 0.70710678118654752f));
                    *(__half2*)((__half*)outv + row * ND + col) = __floats2half2_rn(v0, v1);
                } else {
                    if (row < (size_t)Mreal)
                        *(float2*)((float*)outv + row * ND + col) = make_float2(v0, v1);
                }
            }
        }
    }
}

// ================= finalize: out0 = y0 ; out[c] = R @ y[1:4] =================
__global__ void finalize_kernel(const float* __restrict__ rot, float* __restrict__ out) {
    int n = blockIdx.x, f = threadIdx.x;
    __shared__ float R[9];
    if (f < 9) R[f] = rot[(size_t)n * 9 + f];
    __syncthreads();
    const float* y = g_y + (size_t)n * ODIMN;
    float y0 = y[f], y1 = y[128 + f], y2 = y[256 + f], y3 = y[384 + f];
    float* o = out + (size_t)n * ODIMN;
    o[f] = y0;
#pragma unroll
    for (int c = 0; c < 3; ++c)
        o[(c + 1) * 128 + f] = R[c * 3] * y1 + R[c * 3 + 1] * y2 + R[c * 3 + 2] * y3;
}

// ================= launch =================
extern "C" void kernel_launch(void* const* d_in, const int* in_sizes, int n_in,
                              void* d_out, int out_size) {
    const float* x     = (const float*)d_in[0];
    const float* rot   = (const float*)d_in[1];
    const float* extra = (const float*)d_in[2];
    const float* W1    = (const float*)d_in[3];
    const float* b1    = (const float*)d_in[4];
    const float* W2    = (const float*)d_in[5];
    const float* b2    = (const float*)d_in[6];
    float* out = (float*)d_out;

    const int Mreal  = in_sizes[0] / 512;           // 100000
    const int mTiles = (Mreal + 127) / 128;         // 782
    const int Mpad   = mTiles * 128;                // 100096

    void *px1, *ph, *py, *pw1, *pw2;
    cudaGetSymbolAddress(&px1, g_x1h);
    cudaGetSymbolAddress(&ph,  g_hh);
    cudaGetSymbolAddress(&py,  g_y);
    cudaGetSymbolAddress(&pw1, g_w1t);
    cudaGetSymbolAddress(&pw2, g_w2t);

    const int smemBytes = 65536;
    cudaFuncSetAttribute((gemm_h<K1, HIDN, 1>),   cudaFuncAttributeMaxDynamicSharedMemorySize, smemBytes);
    cudaFuncSetAttribute((gemm_h<HIDN, ODIMN, 0>), cudaFuncAttributeMaxDynamicSharedMemorySize, smemBytes);

    // weights -> transposed half (W1 with matching k-permutation)
    {
        long n1 = (long)HIDN * K1;
        wprep_kernel<1><<<(unsigned)((n1 + 255) / 256), 256>>>(W1, (__half*)pw1, K1, HIDN);
        long n2 = (long)ODIMN * HIDN;
        wprep_kernel<0><<<(unsigned)((n2 + 255) / 256), 256>>>(W2, (__half*)pw2, HIDN, ODIMN);
    }
    // x1 (padded rows zeroed)
    prep_kernel<<<Mpad, 128>>>(x, rot, extra, Mreal);

    // GEMM1: h = gelu(x1 @ W1 + b1)  (half out)
    {
        dim3 grid(HIDN / 128, mTiles);
        gemm_h<K1, HIDN, 1><<<grid, 256, smemBytes>>>((const __half*)px1, (const __half*)pw1,
                                                      b1, ph, Mreal);
    }
    // GEMM2: y = h @ W2 + b2  (fp32 out)
    {
        dim3 grid(ODIMN / 128, mTiles);
        gemm_h<HIDN, ODIMN, 0><<<grid, 256, smemBytes>>>((const __half*)ph, (const __half*)pw2,
                                                         b2, py, Mreal);
    }
    finalize_kernel<<<Mreal, 128>>>(rot, out);
}